// round 3
// baseline (speedup 1.0000x reference)
#include <cuda_runtime.h>

#define CAM_FL  540.0f
#define HALF_W  320.0f
#define HALF_H  240.0f
#define CAM_W   640
#define CAM_H   480
#define PB      512      // particles per block
#define TPB     256      // threads per block
#define REC     16       // floats per survivor record (64B, 16-aligned)

// record layout (floats): [0..7]=wx8 (aligned 8-slot x weights, pre-masked)
//                         [8]=z  [9]=packed(base_x | (ib+2)<<16)  [10..14]=wy[0..4]  [15]=pad

__global__ __launch_bounds__(TPB) void proj_kernel(
    const float* __restrict__ locs,
    const float* __restrict__ pose,
    const float* __restrict__ rotq,
    const float* __restrict__ depth,
    float* __restrict__ out,
    int N)
{
    __shared__ float s_rec[PB][REC];
    __shared__ int   s_cnt;

    const int tid = threadIdx.x;
    const int b   = blockIdx.y;

    if (tid == 0) s_cnt = 0;

    // --- quaternion (normalized, conjugated) -> rotation matrix ---
    float qx = __ldg(rotq + b * 4 + 0);
    float qy = __ldg(rotq + b * 4 + 1);
    float qz = __ldg(rotq + b * 4 + 2);
    float qw = __ldg(rotq + b * 4 + 3);
    float inv = rsqrtf(qx * qx + qy * qy + qz * qz + qw * qw);
    qx = -qx * inv; qy = -qy * inv; qz = -qz * inv; qw = qw * inv;

    const float qx2 = qx * qx, qy2 = qy * qy, qz2 = qz * qz;
    const float qxqy = qx * qy, qxqz = qx * qz, qxqw = qx * qw;
    const float qyqz = qy * qz, qyqw = qy * qw, qzqw = qz * qw;
    const float r00 = 1.f - 2.f * qy2 - 2.f * qz2;
    const float r10 = 2.f * qxqy - 2.f * qzqw;
    const float r20 = 2.f * qxqz + 2.f * qyqw;
    const float r01 = 2.f * qxqy + 2.f * qzqw;
    const float r11 = 1.f - 2.f * qx2 - 2.f * qz2;
    const float r21 = 2.f * qyqz - 2.f * qxqw;
    const float r02 = 2.f * qxqz - 2.f * qyqw;
    const float r12 = 2.f * qyqz + 2.f * qxqw;
    const float r22 = 1.f - 2.f * qx2 - 2.f * qy2;

    const float cx = __ldg(pose + b * 3 + 0);
    const float cy = __ldg(pose + b * 3 + 1);
    const float cz = __ldg(pose + b * 3 + 2);

    __syncthreads();   // s_cnt init visible

    // ---------------- Phase 1: project 2 paired particles/thread, compact ----------------
    const float C1 = 0.60653066f;   // exp(-0.5)
    const float C2 = 0.13533528f;   // exp(-2)

    const int  gpart = blockIdx.x * PB;                 // block's first particle
    const float* lpB = locs + ((long long)b * N + gpart) * 3;
    const int  i0 = 2 * tid;

    float X[2], Y[2], Z[2];
    const bool has1 = (gpart + i0 + 1) < N;
    const bool has0 = (gpart + i0) < N;
    if (has1) {
        // 3x LDG.64, 8B-aligned (block base offset is 24*even bytes)
        const float2 A = *(const float2*)(lpB + i0 * 3);
        const float2 Bv = *(const float2*)(lpB + i0 * 3 + 2);
        const float2 Cv = *(const float2*)(lpB + i0 * 3 + 4);
        X[0] = A.x;  Y[0] = A.y;  Z[0] = Bv.x;
        X[1] = Bv.y; Y[1] = Cv.x; Z[1] = Cv.y;
    } else if (has0) {
        X[0] = lpB[i0 * 3]; Y[0] = lpB[i0 * 3 + 1]; Z[0] = lpB[i0 * 3 + 2];
        X[1] = 0.f; Y[1] = 0.f; Z[1] = -1.f;
    } else {
        X[0] = X[1] = Y[0] = Y[1] = 0.f; Z[0] = Z[1] = -1.f;
    }
    if (!has1) { Z[1] = -1.f; if (!has0) Z[0] = -1.f; }

#pragma unroll
    for (int j = 0; j < 2; j++) {
        const float p0 = X[j] - cx, p1 = Y[j] - cy, p2 = Z[j] - cz;
        const float x = p0 * r00 + p1 * r10 + p2 * r20;
        const float y = p0 * r01 + p1 * r11 + p2 * r21;
        const float z = p0 * r02 + p1 * r12 + p2 * r22;

        bool ok = false;
        float px = 0.f, py = 0.f;
        const bool have = (j == 0) ? has0 : has1;
        if (have && z > 0.f) {
            const float invz = __frcp_rn(z);
            px = x * invz * CAM_FL + HALF_W;
            py = y * invz * CAM_FL + HALF_H;
            ok = (px >= -2.f && px < 642.f && py >= -2.f && py < 482.f);
        }

        // warp-aggregated compaction
        const unsigned m = __ballot_sync(0xffffffffu, ok);
        int idx = 0;
        if (m) {
            const int lane = tid & 31;
            const int lead = __ffs(m) - 1;
            int wbase = 0;
            if (lane == lead) wbase = atomicAdd(&s_cnt, __popc(m));
            wbase = __shfl_sync(0xffffffffu, wbase, lead);
            idx = wbase + __popc(m & ((1u << lane) - 1u));
        }

        if (ok) {
            const float fx = floorf(px), fy = floorf(py);
            const int jb = (int)fx - 2;
            const int ib = (int)fy - 2;
            const int bx = min(max(jb, 0) & ~3, 632);   // aligned 8-slot window start
            const int off = jb - bx;                    // in [-2, 5]

            const float u = fx - px;                    // in [-1, 0]
            const float v = fy - py;

            float* r = s_rec[idx];
            // zero the 8 aligned weight slots
            *(float4*)(r)     = make_float4(0.f, 0.f, 0.f, 0.f);
            *(float4*)(r + 4) = make_float4(0.f, 0.f, 0.f, 0.f);

            // separable Gaussian, factorized
            const float ax  = __expf(-0.5f * u * u);
            const float ex  = __expf(-u);
            const float exi = __frcp_rn(ex);
            const float w0 = ax * exi * exi * C2;
            const float w1 = ax * exi * C1;
            const float w2 = ax;
            const float w3 = ax * ex * C1;
            const float w4 = ax * ex * ex * C2;
            // scatter into aligned slots; slots outside [0,7] are genuinely OOB pixels
            {
                int s;
                s = off + 0; if (s >= 0 && s <= 7) r[s] = w0;
                s = off + 1; if (s >= 0 && s <= 7) r[s] = w1;
                s = off + 2; if (s >= 0 && s <= 7) r[s] = w2;
                s = off + 3; if (s >= 0 && s <= 7) r[s] = w3;
                s = off + 4; if (s >= 0 && s <= 7) r[s] = w4;
            }

            const float ay  = __expf(-0.5f * v * v);
            const float ey  = __expf(-v);
            const float eyi = __frcp_rn(ey);
            r[8]  = z;
            r[9]  = __int_as_float(bx | ((ib + 2) << 16));
            r[10] = ay * eyi * eyi * C2;
            r[11] = ay * eyi * C1;
            r[12] = ay;
            r[13] = ay * ey * C1;
            r[14] = ay * ey * ey * C2;
        }
    }

    __syncthreads();

    // ---------------- Phase 2: one (survivor, row) per work item, vectorized ----------------
    const int cnt   = s_cnt;
    const int total = cnt * 5;
    const float* dimg = depth + b * (CAM_H * CAM_W);
    float*       oimg = out   + b * (CAM_H * CAM_W);

    for (int t = tid; t < total; t += TPB) {
        const int s  = t / 5;
        const int ii = t - s * 5;

        const float* r = s_rec[s];
        const int pk = __float_as_int(r[9]);
        const int bx = pk & 0xffff;
        const int ib = (pk >> 16) - 2;
        const int yy = ib + ii;
        if (yy < 0 || yy >= CAM_H) continue;

        const float z  = r[8];
        const float wy = r[10 + ii];
        const float4 wa = *(const float4*)(r);
        const float4 wb = *(const float4*)(r + 4);

        const int o = yy * CAM_W + bx;
        const float4 d0 = *(const float4*)(dimg + o);
        const float4 d1 = *(const float4*)(dimg + o + 4);

        float4 va, vb;
        va.x = (z <= d0.x) ? wy * wa.x : 0.f;
        va.y = (z <= d0.y) ? wy * wa.y : 0.f;
        va.z = (z <= d0.z) ? wy * wa.z : 0.f;
        va.w = (z <= d0.w) ? wy * wa.w : 0.f;
        vb.x = (z <= d1.x) ? wy * wb.x : 0.f;
        vb.y = (z <= d1.y) ? wy * wb.y : 0.f;
        vb.z = (z <= d1.z) ? wy * wb.z : 0.f;
        vb.w = (z <= d1.w) ? wy * wb.w : 0.f;

        asm volatile("red.global.add.v4.f32 [%0], {%1,%2,%3,%4};"
                     :: "l"(oimg + o), "f"(va.x), "f"(va.y), "f"(va.z), "f"(va.w)
                     : "memory");
        asm volatile("red.global.add.v4.f32 [%0], {%1,%2,%3,%4};"
                     :: "l"(oimg + o + 4), "f"(vb.x), "f"(vb.y), "f"(vb.z), "f"(vb.w)
                     : "memory");
    }
}

extern "C" void kernel_launch(void* const* d_in, const int* in_sizes, int n_in,
                              void* d_out, int out_size) {
    const float* locs  = (const float*)d_in[0];
    const float* pose  = (const float*)d_in[1];
    const float* rotq  = (const float*)d_in[2];
    const float* depth = (const float*)d_in[3];
    float* out = (float*)d_out;

    const int B = in_sizes[1] / 3;           // 4
    const int N = in_sizes[0] / (3 * B);     // 200000

    cudaMemsetAsync(d_out, 0, (size_t)out_size * sizeof(float), 0);

    dim3 grid((N + PB - 1) / PB, B);
    proj_kernel<<<grid, TPB>>>(locs, pose, rotq, depth, out, N);
}